// round 10
// baseline (speedup 1.0000x reference)
#include <cuda_runtime.h>
#include <math.h>

#define Bx 8
#define Tt 12
#define NN 10000
#define EE 160000
#define OD 64
#define FT 80000 /* flat nodes */

#define NBLK 148
#define NTHR 1024
#define TTHR (NBLK * NTHR) /* 151552 */
#define CHUNK 68           /* 148*68 = 10064 >= NN */

typedef unsigned long long ull;

// ---------------- scratch (__device__ globals; no allocation) ----------------
__device__ float g_xT[FT * 16];    // x^T [f][16] (12 used) for gather
__device__ float g_aggN[FT * 12];  // agg of x over normal edges, [f][12]
__device__ float g_aggC[FT * 12];  // agg of x over causal edges, [f][12]
__device__ float g_stats[FT * 8];  // per-node {mh,rhv,ml,rlv,mr,rrv,_,_}
__device__ float2 g_mflag[NN];     // {degN>0, degC>0}
__device__ int g_rowN[NN + 1];
__device__ int g_rowC[NN + 1];
__device__ int g_colN[EE];
__device__ int g_colC[EE];
__device__ int g_degN[NN];
__device__ int g_degC[NN];
__device__ int g_curN[NN];
__device__ int g_curC[NN];
__device__ int g_psumN[NBLK];
__device__ int g_psumC[NBLK];
__device__ unsigned g_cnt;  // grid-barrier counter; reset by epi_kernel
// packed weights: 6 banks x [t:12][pair:32] of {w[d], w[d+32]} (ull = 2 floats)
// banks: 0 Ph1(x->hp) 1 Ph2(a->hp) 2 Pl1(x->lp) 3 Pl2(a->lp) 4 Pl3(c->lp) 5 Pg(x->rp)
__device__ ull g_W[6 * 12 * 32];
__device__ float g_bH0[OD], g_bHm[OD], g_bL0[OD], g_bLm[OD], g_bLc[OD];
// packed epilogue constants: 8 banks x 32 pairs x float4
__device__ float g_Cpk[8 * 32 * 4];

// ---------------- f32x2 helpers ----------------
#define FMA2(d, a, b) asm("fma.rn.f32x2 %0, %1, %2, %0;" : "+l"(d) : "l"(a), "l"(b))
#define ADD2(d, a) asm("add.rn.f32x2 %0, %0, %1;" : "+l"(d) : "l"(a))

__device__ __forceinline__ ull PK2(float lo, float hi) {
    ull r;
    asm("mov.b64 %0, {%1, %2};" : "=l"(r) : "f"(lo), "f"(hi));
    return r;
}
__device__ __forceinline__ void UPK2(float& lo, float& hi, ull v) {
    asm("mov.b64 {%0, %1}, %2;" : "=f"(lo), "=f"(hi) : "l"(v));
}

// ---------------- software grid barrier (all NBLK blocks co-resident) --------
__device__ __forceinline__ void gbar(unsigned phase) {
    __syncthreads();
    if (threadIdx.x == 0) {
        __threadfence();
        atomicAdd(&g_cnt, 1u);
        unsigned target = NBLK * phase;
        while (*(volatile unsigned*)&g_cnt < target) __nanosleep(64);
        __threadfence();
    }
    __syncthreads();
}

// ---------------- K1: persistent pipeline kernel -----------------------------
__global__ void __launch_bounds__(NTHR, 1) pipeline_kernel(
    const float* __restrict__ x, const int* __restrict__ ei, const int* __restrict__ cei,
    const float* __restrict__ W_ht, const float* __restrict__ b_ht,
    const float* __restrict__ W_lt, const float* __restrict__ b_lt,
    const float* __restrict__ Ws_h, const float* __restrict__ Wn_h,
    const float* __restrict__ b_h, const float* __restrict__ Ws_l,
    const float* __restrict__ Wn_l, const float* __restrict__ Wc_l,
    const float* __restrict__ b_l, const float* __restrict__ Whr,
    const float* __restrict__ bhr, const float* __restrict__ Wlr,
    const float* __restrict__ blr, const float* __restrict__ Wg,
    const float* __restrict__ bg, const float* __restrict__ ghn,
    const float* __restrict__ bhn, const float* __restrict__ gln,
    const float* __restrict__ bln, const float* __restrict__ ggn,
    const float* __restrict__ bgn, const float* __restrict__ Wa) {
    const int tid = threadIdx.x;
    const int bid = blockIdx.x;
    const int gtid = bid * NTHR + tid;
    __shared__ int s[256];

    // ===== Phase A: count degrees only (critical path to the scans)
    for (int q = gtid; q < 80000; q += TTHR) {
        if (q < 40000) {
            int4 v = ((const int4*)(ei + EE))[q];
            atomicAdd(&g_degN[v.x], 1);
            atomicAdd(&g_degN[v.y], 1);
            atomicAdd(&g_degN[v.z], 1);
            atomicAdd(&g_degN[v.w], 1);
        } else {
            int4 v = ((const int4*)(cei + EE))[q - 40000];
            atomicAdd(&g_degC[v.x], 1);
            atomicAdd(&g_degC[v.y], 1);
            atomicAdd(&g_degC[v.z], 1);
            atomicAdd(&g_degC[v.w], 1);
        }
    }
    gbar(1);

    // ===== Phase B1: per-block partial sums of degrees
    {
        int base = bid * CHUNK;
        if (tid < 68)
            s[tid] = (base + tid < NN) ? g_degN[base + tid] : 0;
        else if (tid < 128)
            s[tid] = 0;
        else if (tid < 196)
            s[tid] = (base + tid - 128 < NN) ? g_degC[base + tid - 128] : 0;
        else if (tid < 256)
            s[tid] = 0;
        __syncthreads();
#pragma unroll
        for (int off = 64; off > 0; off >>= 1) {
            if (tid < off)
                s[tid] += s[tid + off];
            else if (tid >= 128 && tid < 128 + off)
                s[tid] += s[tid + off];
            __syncthreads();
        }
        if (tid == 0) g_psumN[bid] = s[0];
        if (tid == 128) g_psumC[bid] = s[128];
    }
    gbar(2);

    // ===== Phase B2: exclusive scan of 148 partials
    if (bid == 0 && tid < 64) {
        int lane = tid & 31;
        int* p = (tid < 32) ? g_psumN : g_psumC;
        int carry = 0;
        for (int k = 0; k < 5; k++) {
            int i = k * 32 + lane;
            int v = (i < NBLK) ? p[i] : 0;
            int inc = v;
#pragma unroll
            for (int o = 1; o < 32; o <<= 1) {
                int u = __shfl_up_sync(0xffffffffu, inc, o);
                if (lane >= o) inc += u;
            }
            if (i < NBLK) p[i] = carry + inc - v;
            carry += __shfl_sync(0xffffffffu, inc, 31);
        }
    }
    gbar(3);

    // ===== Phase B3: local inclusive scan -> row offsets
    {
        int base = bid * CHUNK;
        if (tid < 68)
            s[tid] = (base + tid < NN) ? g_degN[base + tid] : 0;
        else if (tid < 128)
            s[tid] = 0;
        else if (tid < 196)
            s[tid] = (base + tid - 128 < NN) ? g_degC[base + tid - 128] : 0;
        else if (tid < 256)
            s[tid] = 0;
        __syncthreads();
#pragma unroll
        for (int off = 1; off < 128; off <<= 1) {
            int v = 0;
            if (tid < 256 && (tid & 127) >= off) v = s[tid - off];
            __syncthreads();
            if (tid < 256) s[tid] += v;
            __syncthreads();
        }
        if (tid < 68) {
            int n = base + tid;
            if (n < NN) g_rowN[n + 1] = g_psumN[bid] + s[tid];
        } else if (tid >= 128 && tid < 196) {
            int n = base + tid - 128;
            if (n < NN) g_rowC[n + 1] = g_psumC[bid] + s[tid];
        }
        if (bid == 0 && tid == 0) {
            g_rowN[0] = 0;
            g_rowC[0] = 0;
        }
    }
    gbar(4);

    // ===== Phase C: fill CSR | transpose x | prep weights (independent work)
    for (int i = gtid; i < 2 * EE + 80000 + 832; i += TTHR) {
        if (i < EE) {
            int dd = __ldg(&ei[EE + i]);
            int p = atomicAdd(&g_curN[dd], 1);
            g_colN[g_rowN[dd] + p] = __ldg(&ei[i]);
        } else if (i < 2 * EE) {
            int j = i - EE;
            int dd = __ldg(&cei[EE + j]);
            int p = atomicAdd(&g_curC[dd], 1);
            g_colC[g_rowC[dd] + p] = __ldg(&cei[j]);
        } else if (i < 2 * EE + 80000) {
            int j = i - 2 * EE;
            int b = j / NN;
            int n = j - b * NN;
            float v[12];
#pragma unroll
            for (int t = 0; t < Tt; t++) v[t] = x[((size_t)b * Tt + t) * NN + n];
            float4* dst = (float4*)(g_xT + (size_t)j * 16);
            dst[0] = make_float4(v[0], v[1], v[2], v[3]);
            dst[1] = make_float4(v[4], v[5], v[6], v[7]);
            dst[2] = make_float4(v[8], v[9], v[10], v[11]);
            dst[3] = make_float4(0.f, 0.f, 0.f, 0.f);
        } else {
            int pid = i - 2 * EE - 80000;  // 0..831
            int t = pid >> 6;
            int d = pid & 63;
            int dl = d & 31;
            int hi = d >> 5;
            if (t < Tt) {
                float s1 = 0.f, s2 = 0.f, s3 = 0.f, s4 = 0.f, s5 = 0.f;
                for (int k = 0; k < 64; k++) {
                    float wht = W_ht[t * 64 + k];
                    float wlt = W_lt[t * 64 + k];
                    s1 += wht * (Ws_h[k * 64 + d] + 0.2f * Whr[k * 64 + d]);
                    s2 += wht * Wn_h[k * 64 + d];
                    s3 += wlt * (Ws_l[k * 64 + d] + 0.2f * Wlr[k * 64 + d]);
                    s4 += wlt * Wn_l[k * 64 + d];
                    s5 += wlt * Wc_l[k * 64 + d];
                }
                float* Wf = (float*)g_W;
                int base = (t * 32 + dl) * 2 + hi;
                Wf[base] = s1;
                Wf[768 + base] = s2;
                Wf[1536 + base] = s3;
                Wf[2304 + base] = s4;
                Wf[3072 + base] = s5;
                Wf[3840 + base] = 2.0f * Wg[t * 64 + d];  // x_res = 2x
            } else {
                float bh0 = b_h[d] + 0.2f * bhr[d];
                float bhm = 0.f;
                float bl0 = b_l[d] + 0.2f * blr[d];
                float blm = 0.f, blc = 0.f;
                for (int k = 0; k < 64; k++) {
                    bh0 += b_ht[k] * (Ws_h[k * 64 + d] + 0.2f * Whr[k * 64 + d]);
                    bhm += b_ht[k] * Wn_h[k * 64 + d];
                    bl0 += b_lt[k] * (Ws_l[k * 64 + d] + 0.2f * Wlr[k * 64 + d]);
                    blm += b_lt[k] * Wn_l[k * 64 + d];
                    blc += b_lt[k] * Wc_l[k * 64 + d];
                }
                g_bH0[d] = bh0;
                g_bHm[d] = bhm;
                g_bL0[d] = bl0;
                g_bLm[d] = blm;
                g_bLc[d] = blc;
            }
        }
    }
    gbar(5);

    // ===== Phase D: gather-aggregate + mflag + cleanup + Cpk packing
    for (int idx = gtid; idx < 340032; idx += TTHR) {
        if (idx < 320000) {
            int t = idx & 15;
            if (t >= Tt) continue;
            int n = idx >> 4;
            int causal = (n >= NN);
            if (causal) n -= NN;
            const int* __restrict__ row = causal ? g_rowC : g_rowN;
            const int* __restrict__ col = causal ? g_colC : g_colN;
            float* __restrict__ dst = causal ? g_aggC : g_aggN;
            int rs = row[n], re = row[n + 1];
            float acc[Bx];
#pragma unroll
            for (int b = 0; b < Bx; b++) acc[b] = 0.f;
#pragma unroll 2
            for (int e = rs; e < re; e++) {
                int c = __ldg(&col[e]);
                const float* p = g_xT + c * 16 + t;
#pragma unroll
                for (int b = 0; b < Bx; b++) acc[b] += __ldg(&p[b * NN * 16]);
            }
            float invd = 1.0f / fmaxf((float)(re - rs), 1.0f);
#pragma unroll
            for (int b = 0; b < Bx; b++) dst[(size_t)(b * NN + n) * 12 + t] = acc[b] * invd;
        } else if (idx < 330000) {
            int z = idx - 320000;  // zero deg/cur (int4 granularity)
            int a = z / 2500;
            int r = z - a * 2500;
            int4 zv = make_int4(0, 0, 0, 0);
            if (a == 0)
                ((int4*)g_degN)[r] = zv;
            else if (a == 1)
                ((int4*)g_degC)[r] = zv;
            else if (a == 2)
                ((int4*)g_curN)[r] = zv;
            else
                ((int4*)g_curC)[r] = zv;
        } else if (idx < 340000) {
            int n = idx - 330000;  // mflag from persistent row arrays
            g_mflag[n] = make_float2((g_rowN[n + 1] > g_rowN[n]) ? 1.f : 0.f,
                                     (g_rowC[n + 1] > g_rowC[n]) ? 1.f : 0.f);
        } else {
            int l = idx - 340000;  // 0..31: pack epilogue constants
            float4* C = (float4*)g_Cpk;
            C[0 * 32 + l] = make_float4(g_bH0[l], g_bH0[l + 32], g_bHm[l], g_bHm[l + 32]);
            C[1 * 32 + l] = make_float4(g_bL0[l], g_bL0[l + 32], g_bLm[l], g_bLm[l + 32]);
            C[2 * 32 + l] = make_float4(g_bLc[l], g_bLc[l + 32], bg[l], bg[l + 32]);
            C[3 * 32 + l] = make_float4(ghn[l], ghn[l + 32], bhn[l], bhn[l + 32]);
            C[4 * 32 + l] = make_float4(gln[l], gln[l + 32], bln[l], bln[l + 32]);
            C[5 * 32 + l] = make_float4(ggn[l], ggn[l + 32], bgn[l], bgn[l + 32]);
            C[6 * 32 + l] =
                make_float4(Wa[l * 2], Wa[(l + 32) * 2], Wa[l * 2 + 1], Wa[(l + 32) * 2 + 1]);
            C[7 * 32 + l] = make_float4(Wa[(64 + l) * 2], Wa[(96 + l) * 2], Wa[(64 + l) * 2 + 1],
                                        Wa[(96 + l) * 2 + 1]);
        }
    }
}

// ---------------- K2a: GEMV kernel (thread-per-node, raw outputs + stats) -----
// Computes hp/lp/rp ONCE, writes raw pair values into the final output slots
// (coalesced along n) and LN stats {m, rsqrt}x3 to g_stats. All weight LDS are
// warp-uniform broadcasts. No epilogue work at all.
#define FB3 (FT / 64) /* 1250 blocks */

__global__ void __launch_bounds__(64, 9) gemv_kernel(float* __restrict__ out,
                                                     const float* __restrict__ x) {
    const int tid = threadIdx.x;

    __shared__ ull sW[2304];   // 6 banks x 12 t x 32 pairs (18.4 KB)
    __shared__ float4 sC[96];  // const banks 0..2 (1.5 KB)
#pragma unroll
    for (int i = 0; i < 18; i++)
        ((ulonglong2*)sW)[tid + i * 64] = ((const ulonglong2*)g_W)[tid + i * 64];
    for (int i = tid; i < 96; i += 64) sC[i] = ((const float4*)g_Cpk)[i];
    __syncthreads();

    const int f = blockIdx.x * 64 + tid;
    const int b = f / NN;
    const int n = f - b * NN;
    const size_t AS = (size_t)Bx * OD * NN;
    const size_t obase = (size_t)(b * OD) * NN + n;
    float* __restrict__ pf = out + obase;           // fused slots (raw rp)
    float* __restrict__ ph = out + AS + obase;      // high slots (raw hp)
    float* __restrict__ pl = out + 2 * AS + obase;  // low slots (raw lp)

    // ---- features
    float vx[12], va[12], vc[12];
#pragma unroll
    for (int t = 0; t < Tt; t++) vx[t] = __ldg(&x[((size_t)b * Tt + t) * NN + n]);
    {
        const float4* pa = (const float4*)(g_aggN + (size_t)f * 12);
        const float4* pc = (const float4*)(g_aggC + (size_t)f * 12);
#pragma unroll
        for (int k = 0; k < 3; k++) {
            float4 a4 = __ldg(&pa[k]);
            float4 c4 = __ldg(&pc[k]);
            va[4 * k] = a4.x;
            va[4 * k + 1] = a4.y;
            va[4 * k + 2] = a4.z;
            va[4 * k + 3] = a4.w;
            vc[4 * k] = c4.x;
            vc[4 * k + 1] = c4.y;
            vc[4 * k + 2] = c4.z;
            vc[4 * k + 3] = c4.w;
        }
    }
    float2 mf = __ldg(&g_mflag[n]);
    const ull pkm = PK2(mf.x, mf.x), pkmc = PK2(mf.y, mf.y);

    ull aH = 0, aH2 = 0, aL = 0, aL2 = 0, aR = 0, aR2 = 0;
#pragma unroll 1
    for (int c = 0; c < 4; c++) {  // hp: banks 0,1 -> raw to high slots
        int p0 = c * 8;
        ull acc[8];
#pragma unroll
        for (int j = 0; j < 8; j++) {
            float4 c0 = sC[p0 + j];
            acc[j] = PK2(c0.x, c0.y);
            FMA2(acc[j], pkm, PK2(c0.z, c0.w));
        }
#pragma unroll
        for (int t = 0; t < Tt; t++) {
            ull qx = PK2(vx[t], vx[t]), qa = PK2(va[t], va[t]);
            const ulonglong2* w0 = (const ulonglong2*)(sW + t * 32 + p0);
            const ulonglong2* w1 = (const ulonglong2*)(sW + 384 + t * 32 + p0);
#pragma unroll
            for (int j = 0; j < 4; j++) {
                ulonglong2 u0 = w0[j], u1 = w1[j];
                FMA2(acc[2 * j], qx, u0.x);
                FMA2(acc[2 * j + 1], qx, u0.y);
                FMA2(acc[2 * j], qa, u1.x);
                FMA2(acc[2 * j + 1], qa, u1.y);
            }
        }
#pragma unroll
        for (int j = 0; j < 8; j++) {
            int p = p0 + j;
            ADD2(aH, acc[j]);
            FMA2(aH2, acc[j], acc[j]);
            float hl, hh;
            UPK2(hl, hh, acc[j]);
            ph[(size_t)p * NN] = hl;
            ph[(size_t)(p + 32) * NN] = hh;
        }
    }
#pragma unroll 1
    for (int c = 0; c < 4; c++) {  // lp: banks 2,3,4 -> raw to low slots
        int p0 = c * 8;
        ull acc[8];
#pragma unroll
        for (int j = 0; j < 8; j++) {
            float4 c1 = sC[32 + p0 + j];
            float4 c2 = sC[64 + p0 + j];
            acc[j] = PK2(c1.x, c1.y);
            FMA2(acc[j], pkm, PK2(c1.z, c1.w));
            FMA2(acc[j], pkmc, PK2(c2.x, c2.y));
        }
#pragma unroll
        for (int t = 0; t < Tt; t++) {
            ull qx = PK2(vx[t], vx[t]), qa = PK2(va[t], va[t]), qc = PK2(vc[t], vc[t]);
            const ulonglong2* w2 = (const ulonglong2*)(sW + 768 + t * 32 + p0);
            const ulonglong2* w3 = (const ulonglong2*)(sW + 1152 + t * 32 + p0);
            const ulonglong2* w4 = (const ulonglong2*)(sW + 1536 + t * 32 + p0);
#pragma unroll
            for (int j = 0; j < 4; j++) {
                ulonglong2 u2 = w2[j], u3 = w3[j], u4 = w4[j];
                FMA2(acc[2 * j], qx, u2.x);
                FMA2(acc[2 * j + 1], qx, u2.y);
                FMA2(acc[2 * j], qa, u3.x);
                FMA2(acc[2 * j + 1], qa, u3.y);
                FMA2(acc[2 * j], qc, u4.x);
                FMA2(acc[2 * j + 1], qc, u4.y);
            }
        }
#pragma unroll
        for (int j = 0; j < 8; j++) {
            int p = p0 + j;
            ADD2(aL, acc[j]);
            FMA2(aL2, acc[j], acc[j]);
            float ll, lh;
            UPK2(ll, lh, acc[j]);
            pl[(size_t)p * NN] = ll;
            pl[(size_t)(p + 32) * NN] = lh;
        }
    }
#pragma unroll 1
    for (int c = 0; c < 4; c++) {  // rp: bank 5 -> raw to fused slots
        int p0 = c * 8;
        ull acc[8];
#pragma unroll
        for (int j = 0; j < 8; j++) {
            float4 c2 = sC[64 + p0 + j];
            acc[j] = PK2(c2.z, c2.w);
        }
#pragma unroll
        for (int t = 0; t < Tt; t++) {
            ull qx = PK2(vx[t], vx[t]);
            const ulonglong2* w5 = (const ulonglong2*)(sW + 1920 + t * 32 + p0);
#pragma unroll
            for (int j = 0; j < 4; j++) {
                ulonglong2 u5 = w5[j];
                FMA2(acc[2 * j], qx, u5.x);
                FMA2(acc[2 * j + 1], qx, u5.y);
            }
        }
#pragma unroll
        for (int j = 0; j < 8; j++) {
            int p = p0 + j;
            ADD2(aR, acc[j]);
            FMA2(aR2, acc[j], acc[j]);
            float rl, rh;
            UPK2(rl, rh, acc[j]);
            pf[(size_t)p * NN] = rl;
            pf[(size_t)(p + 32) * NN] = rh;
        }
    }
    const float inv = 1.0f / 64.0f;
    float u0, u1;
    UPK2(u0, u1, aH);
    float mh = (u0 + u1) * inv;
    UPK2(u0, u1, aH2);
    float vh = (u0 + u1) * inv - mh * mh;
    UPK2(u0, u1, aL);
    float ml = (u0 + u1) * inv;
    UPK2(u0, u1, aL2);
    float vl = (u0 + u1) * inv - ml * ml;
    UPK2(u0, u1, aR);
    float mr = (u0 + u1) * inv;
    UPK2(u0, u1, aR2);
    float vr = (u0 + u1) * inv - mr * mr;
    float4* st = (float4*)g_stats;
    st[f * 2] = make_float4(mh, rsqrtf(vh + 1e-5f), ml, rsqrtf(vl + 1e-5f));
    st[f * 2 + 1] = make_float4(mr, rsqrtf(vr + 1e-5f), 0.f, 0.f);
}

// ---------------- K2b: streaming epilogue (thread-per-node, high occupancy) ---
// Reads raw hp/lp/rp + stats, applies LN + leaky/gelu, writes final high/low,
// accumulates the softmax gate thread-locally (res kept in registers), then
// re-reads high/low (L2-hot) and writes fused.
#define EB ((FT + 255) / 256) /* 313 blocks */

__global__ void __launch_bounds__(256, 2) epi_kernel(float* __restrict__ out,
                                                     const float* __restrict__ ba) {
    const int tid = threadIdx.x;
    if (blockIdx.x == 0 && tid == 0) g_cnt = 0;  // reset grid barrier for next replay

    __shared__ float4 sC[160];  // const banks 3..7 (2.5 KB)
    if (tid < 160) sC[tid] = ((const float4*)g_Cpk)[96 + tid];
    __syncthreads();

    const int f = blockIdx.x * 256 + tid;
    if (f >= FT) return;
    const int b = f / NN;
    const int n = f - b * NN;
    const float ba0 = __ldg(&ba[0]), ba1 = __ldg(&ba[1]);
    const size_t AS = (size_t)Bx * OD * NN;
    const size_t obase = (size_t)(b * OD) * NN + n;
    float* __restrict__ pf = out + obase;
    float* __restrict__ ph = out + AS + obase;
    float* __restrict__ pl = out + 2 * AS + obase;

    float4 s0 = ((const float4*)g_stats)[f * 2];
    float4 s1 = ((const float4*)g_stats)[f * 2 + 1];
    const float mh = s0.x, rhv = s0.y, ml = s0.z, rlv = s0.w, mr = s1.x, rrv = s1.y;

    float resv[64];  // res values live in registers (loops fully unrolled)
    float z0 = 0.f, z1 = 0.f;
#pragma unroll
    for (int p = 0; p < 32; p++) {
        float hl = ph[(size_t)p * NN], hh = ph[(size_t)(p + 32) * NN];
        float ll = pl[(size_t)p * NN], lh = pl[(size_t)(p + 32) * NN];
        float rl = pf[(size_t)p * NN], rh = pf[(size_t)(p + 32) * NN];
        float4 c3 = sC[p], c4 = sC[32 + p], c5 = sC[64 + p], c6 = sC[96 + p], c7 = sC[128 + p];
        float highl = fmaf((hl - mh) * rhv, c3.x, c3.z);
        float highh = fmaf((hh - mh) * rhv, c3.y, c3.w);
        highl = (highl >= 0.f) ? highl : 0.1f * highl;
        highh = (highh >= 0.f) ? highh : 0.1f * highh;
        float lwl = fmaf((ll - ml) * rlv, c4.x, c4.z);
        float lwh = fmaf((lh - ml) * rlv, c4.y, c4.w);
        float lowl = 0.5f * lwl * (1.0f + erff(lwl * 0.70710678118654752f));
        float lowh = 0.5f * lwh * (1.0f + erff(lwh * 0.70710678118654752f));
        resv[2 * p] = fmaf((rl - mr) * rrv, c5.x, c5.z);
        resv[2 * p + 1] = fmaf((rh - mr) * rrv, c5.y, c5.w);
        z0 += highl * c6.x + highh * c6.y + lowl * c7.x + lowh * c7.y;
        z1 += highl * c6.z + highh * c6.w + lowl * c7.z + lowh * c7.w;
        ph[(size_t)p * NN] = highl;
        ph[(size_t)(p + 32) * NN] = highh;
        pl[(size_t)p * NN] = lowl;
        pl[(size_t)(p + 32) * NN] = lowh;
    }
    float a0 = 1.0f / (1.0f + expf((z1 + ba1) - (z0 + ba0)));
    float a1 = 1.0f - a0;
#pragma unroll
    for (int p = 0; p < 32; p++) {
        float hl = ph[(size_t)p * NN], hh = ph[(size_t)(p + 32) * NN];
        float ll = pl[(size_t)p * NN], lh = pl[(size_t)(p + 32) * NN];
        float fl = fmaf(a0, hl, a1 * ll) + 0.3f * (hl + ll) + 0.1f * resv[2 * p];
        float fh = fmaf(a0, hh, a1 * lh) + 0.3f * (hh + lh) + 0.1f * resv[2 * p + 1];
        pf[(size_t)p * NN] = fl;
        pf[(size_t)(p + 32) * NN] = fh;
    }
}

// ---------------- launch ------------------------------------------------------

extern "C" void kernel_launch(void* const* d_in, const int* in_sizes, int n_in, void* d_out,
                              int out_size) {
    const float* x = (const float*)d_in[0];
    const int* ei = (const int*)d_in[1];
    const int* cei = (const int*)d_in[2];
    const float* W_ht = (const float*)d_in[3];
    const float* b_ht = (const float*)d_in[4];
    const float* W_lt = (const float*)d_in[5];
    const float* b_lt = (const float*)d_in[6];
    const float* Ws_h = (const float*)d_in[7];
    const float* Wn_h = (const float*)d_in[8];
    const float* b_h = (const float*)d_in[9];
    const float* Ws_l = (const float*)d_in[10];
    const float* Wn_l = (const float*)d_in[11];
    const float* Wc_l = (const float*)d_in[12];
    const float* b_l = (const float*)d_in[13];
    const float* Whr = (const float*)d_in[14];
    const float* bhr = (const float*)d_in[15];
    const float* Wlr = (const float*)d_in[16];
    const float* blr = (const float*)d_in[17];
    const float* ghn = (const float*)d_in[18];
    const float* bhn = (const float*)d_in[19];
    const float* gln = (const float*)d_in[20];
    const float* bln = (const float*)d_in[21];
    const float* Wa = (const float*)d_in[22];
    const float* ba = (const float*)d_in[23];
    const float* Wg = (const float*)d_in[24];
    const float* bg = (const float*)d_in[25];
    const float* ggn = (const float*)d_in[26];
    const float* bgn = (const float*)d_in[27];
    float* out = (float*)d_out;

    pipeline_kernel<<<NBLK, NTHR>>>(x, ei, cei, W_ht, b_ht, W_lt, b_lt, Ws_h, Wn_h, b_h, Ws_l,
                                    Wn_l, Wc_l, b_l, Whr, bhr, Wlr, blr, Wg, bg, ghn, bhn, gln,
                                    bln, ggn, bgn, Wa);
    gemv_kernel<<<FB3, 64>>>(out, x);
    epi_kernel<<<EB, 256>>>(out, ba);
}

// round 11
// speedup vs baseline: 1.2995x; 1.2995x over previous
#include <cuda_runtime.h>
#include <math.h>

#define Bx 8
#define Tt 12
#define NN 10000
#define EE 160000
#define OD 64
#define FT 80000 /* flat nodes */

#define PBLK 296 /* 2 co-resident blocks per SM */
#define PTHR 512
#define TTHR (PBLK * PTHR) /* 151552 */
#define CHUNK 34           /* 296*34 = 10064 >= NN */

typedef unsigned long long ull;

// ---------------- scratch (__device__ globals; no allocation) ----------------
__device__ float g_xT[FT * 16];    // x^T [f][16] (12 used) for gather
__device__ float g_aggN[FT * 12];  // agg of x over normal edges, [f][12]
__device__ float g_aggC[FT * 12];  // agg of x over causal edges, [f][12]
__device__ float2 g_mflag[NN];     // {degN>0, degC>0}
__device__ int g_rowN[NN + 1];
__device__ int g_rowC[NN + 1];
__device__ int g_colN[EE];
__device__ int g_colC[EE];
__device__ int g_degN[NN];
__device__ int g_degC[NN];
__device__ int g_curN[NN];
__device__ int g_curC[NN];
__device__ int g_psumN[PBLK];
__device__ int g_psumC[PBLK];
__device__ unsigned g_cnt;  // grid-barrier counter; reset by final_kernel
// packed weights: 6 banks x [t:12][pair:32] of {w[d], w[d+32]} (ull = 2 floats)
// banks: 0 Ph1(x->hp) 1 Ph2(a->hp) 2 Pl1(x->lp) 3 Pl2(a->lp) 4 Pl3(c->lp) 5 Pg(x->rp)
__device__ ull g_W[6 * 12 * 32];
__device__ float g_bH0[OD], g_bHm[OD], g_bL0[OD], g_bLm[OD], g_bLc[OD];
// packed epilogue constants: 8 banks x 32 pairs x float4
__device__ float g_Cpk[8 * 32 * 4];

// ---------------- f32x2 helpers ----------------
#define FMA2(d, a, b) asm("fma.rn.f32x2 %0, %1, %2, %0;" : "+l"(d) : "l"(a), "l"(b))
#define ADD2(d, a) asm("add.rn.f32x2 %0, %0, %1;" : "+l"(d) : "l"(a))

__device__ __forceinline__ ull PK2(float lo, float hi) {
    ull r;
    asm("mov.b64 %0, {%1, %2};" : "=l"(r) : "f"(lo), "f"(hi));
    return r;
}
__device__ __forceinline__ void UPK2(float& lo, float& hi, ull v) {
    asm("mov.b64 {%0, %1}, %2;" : "=f"(lo), "=f"(hi) : "l"(v));
}

// ---------------- software grid barrier (all PBLK blocks co-resident) --------
__device__ __forceinline__ void gbar(unsigned phase) {
    __syncthreads();
    if (threadIdx.x == 0) {
        __threadfence();
        atomicAdd(&g_cnt, 1u);
        unsigned target = PBLK * phase;
        while (*(volatile unsigned*)&g_cnt < target) __nanosleep(64);
        __threadfence();
    }
    __syncthreads();
}

// ---------------- K1: persistent pipeline kernel (2 blocks/SM) ---------------
__global__ void __launch_bounds__(PTHR, 2) pipeline_kernel(
    const float* __restrict__ x, const int* __restrict__ ei, const int* __restrict__ cei,
    const float* __restrict__ W_ht, const float* __restrict__ b_ht,
    const float* __restrict__ W_lt, const float* __restrict__ b_lt,
    const float* __restrict__ Ws_h, const float* __restrict__ Wn_h,
    const float* __restrict__ b_h, const float* __restrict__ Ws_l,
    const float* __restrict__ Wn_l, const float* __restrict__ Wc_l,
    const float* __restrict__ b_l, const float* __restrict__ Whr,
    const float* __restrict__ bhr, const float* __restrict__ Wlr,
    const float* __restrict__ blr, const float* __restrict__ Wg,
    const float* __restrict__ bg, const float* __restrict__ ghn,
    const float* __restrict__ bhn, const float* __restrict__ gln,
    const float* __restrict__ bln, const float* __restrict__ ggn,
    const float* __restrict__ bgn, const float* __restrict__ Wa) {
    const int tid = threadIdx.x;
    const int bid = blockIdx.x;
    const int gtid = bid * PTHR + tid;
    __shared__ int s[256];

    // ===== Phase A: transpose x (gather layout) | count degrees | prep weights
    for (int i = gtid; i < 160832; i += TTHR) {
        if (i < 80000) {
            int b = i / NN;
            int n = i - b * NN;
            float v[12];
#pragma unroll
            for (int t = 0; t < Tt; t++) v[t] = x[((size_t)b * Tt + t) * NN + n];
            float4* dst = (float4*)(g_xT + (size_t)i * 16);
            dst[0] = make_float4(v[0], v[1], v[2], v[3]);
            dst[1] = make_float4(v[4], v[5], v[6], v[7]);
            dst[2] = make_float4(v[8], v[9], v[10], v[11]);
            dst[3] = make_float4(0.f, 0.f, 0.f, 0.f);
        } else if (i < 160000) {
            int q = i - 80000;
            if (q < 40000) {
                int4 v = ((const int4*)(ei + EE))[q];
                atomicAdd(&g_degN[v.x], 1);
                atomicAdd(&g_degN[v.y], 1);
                atomicAdd(&g_degN[v.z], 1);
                atomicAdd(&g_degN[v.w], 1);
            } else {
                int4 v = ((const int4*)(cei + EE))[q - 40000];
                atomicAdd(&g_degC[v.x], 1);
                atomicAdd(&g_degC[v.y], 1);
                atomicAdd(&g_degC[v.z], 1);
                atomicAdd(&g_degC[v.w], 1);
            }
        } else {
            int pid = i - 160000;  // 0..831
            int t = pid >> 6;
            int d = pid & 63;
            int dl = d & 31;
            int hi = d >> 5;
            if (t < Tt) {
                float s1 = 0.f, s2 = 0.f, s3 = 0.f, s4 = 0.f, s5 = 0.f;
                for (int k = 0; k < 64; k++) {
                    float wht = W_ht[t * 64 + k];
                    float wlt = W_lt[t * 64 + k];
                    s1 += wht * (Ws_h[k * 64 + d] + 0.2f * Whr[k * 64 + d]);
                    s2 += wht * Wn_h[k * 64 + d];
                    s3 += wlt * (Ws_l[k * 64 + d] + 0.2f * Wlr[k * 64 + d]);
                    s4 += wlt * Wn_l[k * 64 + d];
                    s5 += wlt * Wc_l[k * 64 + d];
                }
                float* Wf = (float*)g_W;
                int base = (t * 32 + dl) * 2 + hi;
                Wf[base] = s1;
                Wf[768 + base] = s2;
                Wf[1536 + base] = s3;
                Wf[2304 + base] = s4;
                Wf[3072 + base] = s5;
                Wf[3840 + base] = 2.0f * Wg[t * 64 + d];  // x_res = 2x
            } else {
                float bh0 = b_h[d] + 0.2f * bhr[d];
                float bhm = 0.f;
                float bl0 = b_l[d] + 0.2f * blr[d];
                float blm = 0.f, blc = 0.f;
                for (int k = 0; k < 64; k++) {
                    bh0 += b_ht[k] * (Ws_h[k * 64 + d] + 0.2f * Whr[k * 64 + d]);
                    bhm += b_ht[k] * Wn_h[k * 64 + d];
                    bl0 += b_lt[k] * (Ws_l[k * 64 + d] + 0.2f * Wlr[k * 64 + d]);
                    blm += b_lt[k] * Wn_l[k * 64 + d];
                    blc += b_lt[k] * Wc_l[k * 64 + d];
                }
                g_bH0[d] = bh0;
                g_bHm[d] = bhm;
                g_bL0[d] = bl0;
                g_bLm[d] = blm;
                g_bLc[d] = blc;
            }
        }
    }
    gbar(1);

    // ===== Phase B1: per-block partial sums of degrees (chunk of 34 nodes)
    {
        int base = bid * CHUNK;
        if (tid < CHUNK)
            s[tid] = (base + tid < NN) ? g_degN[base + tid] : 0;
        else if (tid < 128)
            s[tid] = 0;
        else if (tid < 128 + CHUNK)
            s[tid] = (base + tid - 128 < NN) ? g_degC[base + tid - 128] : 0;
        else if (tid < 256)
            s[tid] = 0;
        __syncthreads();
#pragma unroll
        for (int off = 64; off > 0; off >>= 1) {
            if (tid < off)
                s[tid] += s[tid + off];
            else if (tid >= 128 && tid < 128 + off)
                s[tid] += s[tid + off];
            __syncthreads();
        }
        if (tid == 0) g_psumN[bid] = s[0];
        if (tid == 128) g_psumC[bid] = s[128];
    }
    gbar(2);

    // ===== Phase B2: exclusive scan of 296 partials (block 0, warps 0 and 1)
    if (bid == 0 && tid < 64) {
        int lane = tid & 31;
        int* p = (tid < 32) ? g_psumN : g_psumC;
        int carry = 0;
        for (int k = 0; k < 10; k++) {
            int i = k * 32 + lane;
            int v = (i < PBLK) ? p[i] : 0;
            int inc = v;
#pragma unroll
            for (int o = 1; o < 32; o <<= 1) {
                int u = __shfl_up_sync(0xffffffffu, inc, o);
                if (lane >= o) inc += u;
            }
            if (i < PBLK) p[i] = carry + inc - v;
            carry += __shfl_sync(0xffffffffu, inc, 31);
        }
    }
    gbar(3);

    // ===== Phase B3: local inclusive scan -> row offsets
    {
        int base = bid * CHUNK;
        if (tid < CHUNK)
            s[tid] = (base + tid < NN) ? g_degN[base + tid] : 0;
        else if (tid < 128)
            s[tid] = 0;
        else if (tid < 128 + CHUNK)
            s[tid] = (base + tid - 128 < NN) ? g_degC[base + tid - 128] : 0;
        else if (tid < 256)
            s[tid] = 0;
        __syncthreads();
#pragma unroll
        for (int off = 1; off < 64; off <<= 1) {
            int v = 0;
            if (tid < 256 && (tid & 127) >= off) v = s[tid - off];
            __syncthreads();
            if (tid < 256) s[tid] += v;
            __syncthreads();
        }
        if (tid < CHUNK) {
            int n = base + tid;
            if (n < NN) g_rowN[n + 1] = g_psumN[bid] + s[tid];
        } else if (tid >= 128 && tid < 128 + CHUNK) {
            int n = base + tid - 128;
            if (n < NN) g_rowC[n + 1] = g_psumC[bid] + s[tid];
        }
        if (bid == 0 && tid == 0) {
            g_rowN[0] = 0;
            g_rowC[0] = 0;
        }
    }
    gbar(4);

    // ===== Phase C: fill CSR columns | pack epilogue constants
    for (int i = gtid; i < 2 * EE + 32; i += TTHR) {
        if (i < EE) {
            int dd = __ldg(&ei[EE + i]);
            int p = atomicAdd(&g_curN[dd], 1);
            g_colN[g_rowN[dd] + p] = __ldg(&ei[i]);
        } else if (i < 2 * EE) {
            int j = i - EE;
            int dd = __ldg(&cei[EE + j]);
            int p = atomicAdd(&g_curC[dd], 1);
            g_colC[g_rowC[dd] + p] = __ldg(&cei[j]);
        } else {
            int l = i - 2 * EE;  // 0..31
            float4* C = (float4*)g_Cpk;
            C[0 * 32 + l] = make_float4(g_bH0[l], g_bH0[l + 32], g_bHm[l], g_bHm[l + 32]);
            C[1 * 32 + l] = make_float4(g_bL0[l], g_bL0[l + 32], g_bLm[l], g_bLm[l + 32]);
            C[2 * 32 + l] = make_float4(g_bLc[l], g_bLc[l + 32], bg[l], bg[l + 32]);
            C[3 * 32 + l] = make_float4(ghn[l], ghn[l + 32], bhn[l], bhn[l + 32]);
            C[4 * 32 + l] = make_float4(gln[l], gln[l + 32], bln[l], bln[l + 32]);
            C[5 * 32 + l] = make_float4(ggn[l], ggn[l + 32], bgn[l], bgn[l + 32]);
            C[6 * 32 + l] =
                make_float4(Wa[l * 2], Wa[(l + 32) * 2], Wa[l * 2 + 1], Wa[(l + 32) * 2 + 1]);
            C[7 * 32 + l] = make_float4(Wa[(64 + l) * 2], Wa[(96 + l) * 2], Wa[(64 + l) * 2 + 1],
                                        Wa[(96 + l) * 2 + 1]);
        }
    }
    gbar(5);

    // ===== Phase D: gather-aggregate (compact [f][12]) + mflag + cleanup
    for (int idx = gtid; idx < 340000; idx += TTHR) {
        if (idx < 320000) {
            int t = idx & 15;
            if (t >= Tt) continue;
            int n = idx >> 4;
            int causal = (n >= NN);
            if (causal) n -= NN;
            const int* __restrict__ row = causal ? g_rowC : g_rowN;
            const int* __restrict__ col = causal ? g_colC : g_colN;
            float* __restrict__ dst = causal ? g_aggC : g_aggN;
            int rs = row[n], re = row[n + 1];
            float acc[Bx];
#pragma unroll
            for (int b = 0; b < Bx; b++) acc[b] = 0.f;
#pragma unroll 2
            for (int e = rs; e < re; e++) {
                int c = __ldg(&col[e]);
                const float* p = g_xT + c * 16 + t;
#pragma unroll
                for (int b = 0; b < Bx; b++) acc[b] += __ldg(&p[b * NN * 16]);
            }
            float invd = 1.0f / fmaxf((float)(re - rs), 1.0f);
#pragma unroll
            for (int b = 0; b < Bx; b++) dst[(size_t)(b * NN + n) * 12 + t] = acc[b] * invd;
        } else if (idx < 330000) {
            int z = idx - 320000;  // zero deg/cur (int4 granularity)
            int a = z / 2500;
            int r = z - a * 2500;
            int4 zv = make_int4(0, 0, 0, 0);
            if (a == 0)
                ((int4*)g_degN)[r] = zv;
            else if (a == 1)
                ((int4*)g_degC)[r] = zv;
            else if (a == 2)
                ((int4*)g_curN)[r] = zv;
            else
                ((int4*)g_curC)[r] = zv;
        } else {
            int n = idx - 330000;  // mflag from persistent row arrays
            g_mflag[n] = make_float2((g_rowN[n + 1] > g_rowN[n]) ? 1.f : 0.f,
                                     (g_rowC[n + 1] > g_rowC[n]) ? 1.f : 0.f);
        }
    }
}

// ---------------- K2: fused epilogue (thread-per-node, raw staging) -----------
// 64 thr/block, thread = one flat node. Pass A: compute hp/lp/rp ONCE, write
// RAW pair values into the final high/low/fused slots (coalesced along n)
// while accumulating LN stats. Pass 2: read raw hp/lp back (same thread,
// L2-hot), LN + activations in place, gate partials. Pass 3: read raw rp +
// transformed high/low back, fuse. All weight LDS are warp-uniform LDS.128
// broadcasts; no GEMV work is ever repeated.
#define FB3 (FT / 64) /* 1250 blocks */

__global__ void __launch_bounds__(64, 8) final_kernel(float* __restrict__ out,
                                                      const float* __restrict__ x,
                                                      const float* __restrict__ ba) {
    const int tid = threadIdx.x;
    if (blockIdx.x == 0 && tid == 0) g_cnt = 0;  // reset grid barrier for next replay

    __shared__ ull sW[2304];    // 6 banks x 12 t x 32 pairs (18.4 KB)
    __shared__ float4 sC[256];  // 8 const banks x 32 pairs  (4 KB)
#pragma unroll
    for (int i = 0; i < 18; i++)
        ((ulonglong2*)sW)[tid + i * 64] = ((const ulonglong2*)g_W)[tid + i * 64];
#pragma unroll
    for (int i = 0; i < 4; i++) sC[tid + i * 64] = ((const float4*)g_Cpk)[tid + i * 64];
    __syncthreads();

    const int f = blockIdx.x * 64 + tid;
    const int b = f / NN;
    const int n = f - b * NN;
    const float ba0 = __ldg(&ba[0]), ba1 = __ldg(&ba[1]);
    const size_t AS = (size_t)Bx * OD * NN;
    const size_t obase = (size_t)(b * OD) * NN + n;
    float* __restrict__ pf = out + obase;           // fused slots (raw rp)
    float* __restrict__ ph = out + AS + obase;      // high slots (raw hp)
    float* __restrict__ pl = out + 2 * AS + obase;  // low slots (raw lp)

    // ---- features (held in registers across passes)
    float vx[12], va[12], vc[12];
#pragma unroll
    for (int t = 0; t < Tt; t++) vx[t] = __ldg(&x[((size_t)b * Tt + t) * NN + n]);
    {
        const float4* pa = (const float4*)(g_aggN + (size_t)f * 12);
        const float4* pc = (const float4*)(g_aggC + (size_t)f * 12);
#pragma unroll
        for (int k = 0; k < 3; k++) {
            float4 a4 = __ldg(&pa[k]);
            float4 c4 = __ldg(&pc[k]);
            va[4 * k] = a4.x;
            va[4 * k + 1] = a4.y;
            va[4 * k + 2] = a4.z;
            va[4 * k + 3] = a4.w;
            vc[4 * k] = c4.x;
            vc[4 * k + 1] = c4.y;
            vc[4 * k + 2] = c4.z;
            vc[4 * k + 3] = c4.w;
        }
    }
    float2 mf = __ldg(&g_mflag[n]);
    const ull pkm = PK2(mf.x, mf.x), pkmc = PK2(mf.y, mf.y);

    // ================= pass A: single GEMV, raw staging + stats ===============
    ull aH = 0, aH2 = 0, aL = 0, aL2 = 0, aR = 0, aR2 = 0;
#pragma unroll 1
    for (int c = 0; c < 4; c++) {  // hp: banks 0,1 -> raw to high slots
        int p0 = c * 8;
        ull acc[8];
#pragma unroll
        for (int j = 0; j < 8; j++) {
            float4 c0 = sC[p0 + j];
            acc[j] = PK2(c0.x, c0.y);
            FMA2(acc[j], pkm, PK2(c0.z, c0.w));
        }
#pragma unroll
        for (int t = 0; t < Tt; t++) {
            ull qx = PK2(vx[t], vx[t]), qa = PK2(va[t], va[t]);
            const ulonglong2* w0 = (const ulonglong2*)(sW + t * 32 + p0);
            const ulonglong2* w1 = (const ulonglong2*)(sW + 384 + t * 32 + p0);
#pragma unroll
            for (int j = 0; j < 4; j++) {
                ulonglong2 u0 = w0[j], u1 = w1[j];
                FMA2(acc[2 * j], qx, u0.x);
                FMA2(acc[2 * j + 1], qx, u0.y);
                FMA2(acc[2 * j], qa, u1.x);
                FMA2(acc[2 * j + 1], qa, u1.y);
            }
        }
#pragma unroll
        for (int j = 0; j < 8; j++) {
            int p = p0 + j;
            ADD2(aH, acc[j]);
            FMA2(aH2, acc[j], acc[j]);
            float hl, hh;
            UPK2(hl, hh, acc[j]);
            ph[(size_t)p * NN] = hl;
            ph[(size_t)(p + 32) * NN] = hh;
        }
    }
#pragma unroll 1
    for (int c = 0; c < 4; c++) {  // lp: banks 2,3,4 -> raw to low slots
        int p0 = c * 8;
        ull acc[8];
#pragma unroll
        for (int j = 0; j < 8; j++) {
            float4 c1 = sC[32 + p0 + j];
            float4 c2 = sC[64 + p0 + j];
            acc[j] = PK2(c1.x, c1.y);
            FMA2(acc[j], pkm, PK2(c1.z, c1.w));
            FMA2(acc[j], pkmc, PK2(c2.x, c2.y));
        }
#pragma unroll
        for (int t = 0; t < Tt; t++) {
            ull qx = PK2(vx[t], vx[t]), qa = PK2(va[t], va[t]), qc = PK2(vc[t], vc[t]);
            const ulonglong2* w2 = (const ulonglong2*)(sW + 768 + t * 32 + p0);
            const ulonglong2* w3 = (const ulonglong2*)(sW + 1152 + t * 32 + p0);
            const ulonglong2* w4 = (const ulonglong2*)(sW + 1536 + t * 32 + p0);
#pragma unroll
            for (int j = 0; j < 4; j++) {
                ulonglong2 u2 = w2[j], u3 = w3[j], u4 = w4[j];
                FMA2(acc[2 * j], qx, u2.x);
                FMA2(acc[2 * j + 1], qx, u2.y);
                FMA2(acc[2 * j], qa, u3.x);
                FMA2(acc[2 * j + 1], qa, u3.y);
                FMA2(acc[2 * j], qc, u4.x);
                FMA2(acc[2 * j + 1], qc, u4.y);
            }
        }
#pragma unroll
        for (int j = 0; j < 8; j++) {
            int p = p0 + j;
            ADD2(aL, acc[j]);
            FMA2(aL2, acc[j], acc[j]);
            float ll, lh;
            UPK2(ll, lh, acc[j]);
            pl[(size_t)p * NN] = ll;
            pl[(size_t)(p + 32) * NN] = lh;
        }
    }
#pragma unroll 1
    for (int c = 0; c < 4; c++) {  // rp: bank 5 -> raw to fused slots
        int p0 = c * 8;
        ull acc[8];
#pragma unroll
        for (int j = 0; j < 8; j++) {
            float4 c2 = sC[64 + p0 + j];
            acc[j] = PK2(c2.z, c2.w);
        }
#pragma unroll
        for (int t = 0; t < Tt; t++) {
            ull qx = PK2(vx[t], vx[t]);
            const ulonglong2* w5 = (const ulonglong2*)(sW + 1920 + t * 32 + p0);
#pragma unroll
            for (int j = 0; j < 4; j++) {
                ulonglong2 u5 = w5[j];
                FMA2(acc[2 * j], qx, u5.x);
                FMA2(acc[2 * j + 1], qx, u5.y);
            }
        }
#pragma unroll
        for (int j = 0; j < 8; j++) {
            int p = p0 + j;
            ADD2(aR, acc[j]);
            FMA2(aR2, acc[j], acc[j]);
            float rl, rh;
            UPK2(rl, rh, acc[j]);
            pf[(size_t)p * NN] = rl;
            pf[(size_t)(p + 32) * NN] = rh;
        }
    }
    const float inv = 1.0f / 64.0f;
    float u0, u1;
    UPK2(u0, u1, aH);
    float mh = (u0 + u1) * inv;
    UPK2(u0, u1, aH2);
    float vh = (u0 + u1) * inv - mh * mh;
    UPK2(u0, u1, aL);
    float ml = (u0 + u1) * inv;
    UPK2(u0, u1, aL2);
    float vl = (u0 + u1) * inv - ml * ml;
    UPK2(u0, u1, aR);
    float mr = (u0 + u1) * inv;
    UPK2(u0, u1, aR2);
    float vr = (u0 + u1) * inv - mr * mr;
    float rhv = rsqrtf(vh + 1e-5f), rlv = rsqrtf(vl + 1e-5f), rrv = rsqrtf(vr + 1e-5f);

    // ================= pass 2: read raw hp/lp, transform in place, gate =======
    float z0 = 0.f, z1 = 0.f;
#pragma unroll 4
    for (int p = 0; p < 32; p++) {
        float4 c3 = sC[96 + p], c4 = sC[128 + p], c6 = sC[192 + p], c7 = sC[224 + p];
        float hl = ph[(size_t)p * NN], hh = ph[(size_t)(p + 32) * NN];
        float ll = pl[(size_t)p * NN], lh = pl[(size_t)(p + 32) * NN];
        float highl = fmaf((hl - mh) * rhv, c3.x, c3.z);
        float highh = fmaf((hh - mh) * rhv, c3.y, c3.w);
        highl = (highl >= 0.f) ? highl : 0.1f * highl;
        highh = (highh >= 0.f) ? highh : 0.1f * highh;
        float lwl = fmaf((ll - ml) * rlv, c4.x, c4.z);
        float lwh = fmaf((lh - ml) * rlv, c4.y, c4.w);
        float lowl = 0.5f * lwl * (1.0f + erff(lwl * 0.70710678118654752f));
        float lowh = 0.5f * lwh * (1.0f + erff(lwh * 0.70710678118654752f));
        z0 += highl * c6.x + highh * c6.y + lowl * c7.x + lowh * c7.y;
        z1 += highl * c6.z + highh * c6.w + lowl * c7.z + lowh * c7.w;
        ph[(size_t)p * NN] = highl;
        ph[(size_t)(p + 32) * NN] = highh;
        pl[(size_t)p * NN] = lowl;
        pl[(size_t)(p + 32) * NN] = lowh;
    }
    float a0 = 1.0f / (1.0f + expf((z1 + ba1) - (z0 + ba0)));
    float a1 = 1.0f - a0;

    // ================= pass 3: read raw rp + high/low back, fuse ==============
#pragma unroll 4
    for (int p = 0; p < 32; p++) {
        float4 c5 = sC[160 + p];
        float rl = pf[(size_t)p * NN], rh = pf[(size_t)(p + 32) * NN];
        float resl = fmaf((rl - mr) * rrv, c5.x, c5.z);
        float resh = fmaf((rh - mr) * rrv, c5.y, c5.w);
        float hl = ph[(size_t)p * NN], hh = ph[(size_t)(p + 32) * NN];
        float ll = pl[(size_t)p * NN], lh = pl[(size_t)(p + 32) * NN];
        float fl = fmaf(a0, hl, a1 * ll) + 0.3f * (hl + ll) + 0.1f * resl;
        float fh = fmaf(a0, hh, a1 * lh) + 0.3f * (hh + lh) + 0.1f * resh;
        pf[(size_t)p * NN] = fl;
        pf[(size_t)(p + 32) * NN] = fh;
    }
}

// ---------------- launch ------------------------------------------------------

extern "C" void kernel_launch(void* const* d_in, const int* in_sizes, int n_in, void* d_out,
                              int out_size) {
    const float* x = (const float*)d_in[0];
    const int* ei = (const int*)d_in[1];
    const int* cei = (const int*)d_in[2];
    const float* W_ht = (const float*)d_in[3];
    const float* b_ht = (const float*)d_in[4];
    const float* W_lt = (const float*)d_in[5];
    const float* b_lt = (const float*)d_in[6];
    const float* Ws_h = (const float*)d_in[7];
    const float* Wn_h = (const float*)d_in[8];
    const float* b_h = (const float*)d_in[9];
    const float* Ws_l = (const float*)d_in[10];
    const float* Wn_l = (const float*)d_in[11];
    const float* Wc_l = (const float*)d_in[12];
    const float* b_l = (const float*)d_in[13];
    const float* Whr = (const float*)d_in[14];
    const float* bhr = (const float*)d_in[15];
    const float* Wlr = (const float*)d_in[16];
    const float* blr = (const float*)d_in[17];
    const float* ghn = (const float*)d_in[18];
    const float* bhn = (const float*)d_in[19];
    const float* gln = (const float*)d_in[20];
    const float* bln = (const float*)d_in[21];
    const float* Wa = (const float*)d_in[22];
    const float* ba = (const float*)d_in[23];
    const float* Wg = (const float*)d_in[24];
    const float* bg = (const float*)d_in[25];
    const float* ggn = (const float*)d_in[26];
    const float* bgn = (const float*)d_in[27];
    float* out = (float*)d_out;

    pipeline_kernel<<<PBLK, PTHR>>>(x, ei, cei, W_ht, b_ht, W_lt, b_lt, Ws_h, Wn_h, b_h, Ws_l,
                                    Wn_l, Wc_l, b_l, Whr, bhr, Wlr, blr, Wg, bg, ghn, bhn, gln,
                                    bln, ggn, bgn, Wa);
    final_kernel<<<FB3, 64>>>(out, x, ba);
}